// round 1
// baseline (speedup 1.0000x reference)
#include <cuda_runtime.h>

// Problem constants: B=8, L=256, Z=16, H=256
//   stage1: sw[(b,x)][o*256+j] = sum_i start[(b,x)][i] * W[i][o*256+j]      (NN GEMM 2048x65536x256)
//   stage2: se[(b,x)][y*256+o] = sum_j end[b][y][j]   * sw[(b,x)][o*256+j] (NT GEMM 256x256x256, 2048 batches)
//   stage3: out[(b,x,y)*16+z]  = sum_o se[(b,x)][y*256+o] * cls[b][z*256+o]

// 537 MB scratch each — static device globals (allocation-guard legal).
__device__ float g_sw[134217728];   // 2048 * 65536
__device__ float g_se[134217728];   // 2048 * 65536

#define TILE 128
#define KT   8

// ---------------------------------------------------------------------------
// Stage 1: C = A(MxK, row-major) @ B(KxN, row-major), writes g_sw.
// M=2048, N=65536, K=256. Block tile 128x128, 256 threads, 8x8 per thread.
// ---------------------------------------------------------------------------
__global__ __launch_bounds__(256, 2)
void gemm_nn_stage1(const float* __restrict__ A, const float* __restrict__ Bm)
{
    const int M = 2048, N = 65536, K = 256; (void)M;
    __shared__ float As[KT][TILE];
    __shared__ float Bs[KT][TILE];

    int tid = threadIdx.x;
    int tx = tid & 15;
    int ty = tid >> 4;
    int m0 = blockIdx.y * TILE;
    int n0 = blockIdx.x * TILE;

    // A loader: transpose into As. lr = row within tile, lc = k offset (0 or 4)
    int lr = tid >> 1;
    int lc = (tid & 1) * 4;
    // B loader: direct float4 rows. bk = k row, bn = col offset
    int bk = tid >> 5;
    int bn = (tid & 31) * 4;

    float acc[8][8];
#pragma unroll
    for (int i = 0; i < 8; i++)
#pragma unroll
        for (int j = 0; j < 8; j++) acc[i][j] = 0.f;

    for (int k0 = 0; k0 < K; k0 += KT) {
        float4 av = *(const float4*)(A + (long)(m0 + lr) * K + k0 + lc);
        As[lc + 0][lr] = av.x;
        As[lc + 1][lr] = av.y;
        As[lc + 2][lr] = av.z;
        As[lc + 3][lr] = av.w;

        float4 bv = *(const float4*)(Bm + (long)(k0 + bk) * N + n0 + bn);
        *(float4*)&Bs[bk][bn] = bv;
        __syncthreads();

#pragma unroll
        for (int kk = 0; kk < KT; kk++) {
            float a[8], b[8];
            *(float4*)(a)     = *(const float4*)&As[kk][ty * 8];
            *(float4*)(a + 4) = *(const float4*)&As[kk][ty * 8 + 4];
            *(float4*)(b)     = *(const float4*)&Bs[kk][tx * 8];
            *(float4*)(b + 4) = *(const float4*)&Bs[kk][tx * 8 + 4];
#pragma unroll
            for (int i = 0; i < 8; i++)
#pragma unroll
                for (int j = 0; j < 8; j++)
                    acc[i][j] = fmaf(a[i], b[j], acc[i][j]);
        }
        __syncthreads();
    }

#pragma unroll
    for (int i = 0; i < 8; i++) {
        long row = m0 + ty * 8 + i;
        float4* cp = (float4*)(g_sw + row * (long)N + n0 + tx * 8);
        cp[0] = make_float4(acc[i][0], acc[i][1], acc[i][2], acc[i][3]);
        cp[1] = make_float4(acc[i][4], acc[i][5], acc[i][6], acc[i][7]);
    }
}

// ---------------------------------------------------------------------------
// Stage 2: batched NT GEMM. batch = b*256 + x (blockIdx.z).
//   A = end[b]        (256 x 256, row-major, [y][j])
//   B = g_sw[batch]   (256 x 256, row-major, [o][j])   -> contract over j
//   C = g_se[batch]   ([y][o])
// Tiles: 2x2 of 128x128 per batch.
// ---------------------------------------------------------------------------
__global__ __launch_bounds__(256, 2)
void gemm_nt_stage2(const float* __restrict__ endl)
{
    const int K = 256, N = 256;
    long batch = blockIdx.z;
    const float* A = endl + (batch >> 8) * 65536;      // end[b]
    const float* Bm = g_sw + batch * 65536;            // sw[(b,x)]
    float* C = g_se + batch * 65536;                   // se[(b,x)]

    __shared__ float As[KT][TILE];
    __shared__ float Bs[KT][TILE];

    int tid = threadIdx.x;
    int tx = tid & 15;
    int ty = tid >> 4;
    int m0 = blockIdx.y * TILE;
    int n0 = blockIdx.x * TILE;

    int lr = tid >> 1;
    int lc = (tid & 1) * 4;

    float acc[8][8];
#pragma unroll
    for (int i = 0; i < 8; i++)
#pragma unroll
        for (int j = 0; j < 8; j++) acc[i][j] = 0.f;

    for (int k0 = 0; k0 < K; k0 += KT) {
        float4 av = *(const float4*)(A + (long)(m0 + lr) * K + k0 + lc);
        As[lc + 0][lr] = av.x;
        As[lc + 1][lr] = av.y;
        As[lc + 2][lr] = av.z;
        As[lc + 3][lr] = av.w;

        float4 bv = *(const float4*)(Bm + (long)(n0 + lr) * K + k0 + lc);
        Bs[lc + 0][lr] = bv.x;
        Bs[lc + 1][lr] = bv.y;
        Bs[lc + 2][lr] = bv.z;
        Bs[lc + 3][lr] = bv.w;
        __syncthreads();

#pragma unroll
        for (int kk = 0; kk < KT; kk++) {
            float a[8], b[8];
            *(float4*)(a)     = *(const float4*)&As[kk][ty * 8];
            *(float4*)(a + 4) = *(const float4*)&As[kk][ty * 8 + 4];
            *(float4*)(b)     = *(const float4*)&Bs[kk][tx * 8];
            *(float4*)(b + 4) = *(const float4*)&Bs[kk][tx * 8 + 4];
#pragma unroll
            for (int i = 0; i < 8; i++)
#pragma unroll
                for (int j = 0; j < 8; j++)
                    acc[i][j] = fmaf(a[i], b[j], acc[i][j]);
        }
        __syncthreads();
    }

#pragma unroll
    for (int i = 0; i < 8; i++) {
        long row = m0 + ty * 8 + i;
        float4* cp = (float4*)(C + row * (long)N + n0 + tx * 8);
        cp[0] = make_float4(acc[i][0], acc[i][1], acc[i][2], acc[i][3]);
        cp[1] = make_float4(acc[i][4], acc[i][5], acc[i][6], acc[i][7]);
    }
}

// ---------------------------------------------------------------------------
// Stage 3: out[row*16+z] = sum_o se[row][o] * cls[b][z][o]
// row = (b,x,y) in [0, 524288). 256 rows per block, cls[b] (16x256) in smem.
// ---------------------------------------------------------------------------
__global__ __launch_bounds__(256)
void stage3_kernel(const float* __restrict__ cls, float* __restrict__ out)
{
    __shared__ float cs[16 * 256];
    int b = blockIdx.x >> 8;                   // 256 blocks per batch b
    const float* clsb = cls + (long)b * 16 * 256;
#pragma unroll
    for (int i = threadIdx.x; i < 16 * 256; i += 256) cs[i] = clsb[i];
    __syncthreads();

    long row = (long)blockIdx.x * 256 + threadIdx.x;
    const float4* ser = (const float4*)(g_se + row * 256);

    float acc[16];
#pragma unroll
    for (int z = 0; z < 16; z++) acc[z] = 0.f;

    for (int k4 = 0; k4 < 64; k4++) {
        float4 v = ser[k4];
        int kb = k4 * 4;
#pragma unroll
        for (int z = 0; z < 16; z++) {
            const float* c = cs + z * 256 + kb;
            acc[z] = fmaf(v.x, c[0], acc[z]);
            acc[z] = fmaf(v.y, c[1], acc[z]);
            acc[z] = fmaf(v.z, c[2], acc[z]);
            acc[z] = fmaf(v.w, c[3], acc[z]);
        }
    }

    float4* o = (float4*)(out + row * 16);
    o[0] = make_float4(acc[0],  acc[1],  acc[2],  acc[3]);
    o[1] = make_float4(acc[4],  acc[5],  acc[6],  acc[7]);
    o[2] = make_float4(acc[8],  acc[9],  acc[10], acc[11]);
    o[3] = make_float4(acc[12], acc[13], acc[14], acc[15]);
}

extern "C" void kernel_launch(void* const* d_in, const int* in_sizes, int n_in,
                              void* d_out, int out_size)
{
    const float* start = (const float*)d_in[0];   // [8,256,256]
    const float* endl  = (const float*)d_in[1];   // [8,256,256]
    const float* cls   = (const float*)d_in[2];   // [8,16,256]
    const float* W     = (const float*)d_in[3];   // [256,256,256]
    float* out = (float*)d_out;                   // [8,256,256,16] fp32

    // Stage 1: 2048 x 65536 x 256 NN GEMM -> g_sw
    dim3 g1(65536 / TILE, 2048 / TILE, 1);
    gemm_nn_stage1<<<g1, 256>>>(start, W);

    // Stage 2: 2048 batches of 256x256x256 NT GEMM -> g_se
    dim3 g2(256 / TILE, 256 / TILE, 2048);
    gemm_nt_stage2<<<g2, 256>>>(endl);

    // Stage 3: contract o with cls -> out
    stage3_kernel<<<2048, 256>>>(cls, out);
}

// round 3
// speedup vs baseline: 9.3191x; 9.3191x over previous
#include <cuda_runtime.h>

// Problem: B=8, L=256, Z=16, H=256
// Reassociated contraction order (12.9 GFLOP total vs 142 GFLOP naive):
//   A: Wc[bz][i][j] = sum_o cls[bz][o] * W[i][o][j]         (per i: GEMM 128x256x256)
//   B: t[b][x][z][j] = sum_i start[b][x][i] * Wc[bz][i][j]  (per bz: GEMM 256x256x256 NN)
//   C: out[b][x][y][z] = sum_j t[b][x][z][j] * end[b][y][j] (per b:  GEMM 4096x256x256 NT)

// Scratch: 33.5 MB each (fits L2).
__device__ float g_wc[8388608];   // [bz=128][i=256][j=256]
__device__ float g_t [8388608];   // [b=8][x=256][z=16][j=256]  (== [m=x*16+z][j] per b)

#define TILE 128
#define KT   8

// ---------------------------------------------------------------------------
// Kernel A: per i (blockIdx.z), C[bz][j] = cls[bz][:] @ W[i][:][:]
// M=128 (one tile), N=256 (2 tiles), K=256. Writes g_wc[bz*65536 + i*256 + j].
// ---------------------------------------------------------------------------
__global__ __launch_bounds__(256, 2)
void kernA(const float* __restrict__ cls, const float* __restrict__ W)
{
    const int K = 256;
    int i_dim = blockIdx.z;
    const float* A  = cls;                         // [128][256]
    const float* Bm = W + (long)i_dim * 65536;     // [o=256][j=256]

    __shared__ float As[KT][TILE];
    __shared__ float Bs[KT][TILE];

    int tid = threadIdx.x;
    int tx = tid & 15, ty = tid >> 4;
    int n0 = blockIdx.x * TILE;

    int lr = tid >> 1;            // 0..127
    int lc = (tid & 1) * 4;       // 0 or 4
    int bk = tid >> 5;            // 0..7
    int bn = (tid & 31) * 4;      // 0..124

    float acc[8][8];
#pragma unroll
    for (int i = 0; i < 8; i++)
#pragma unroll
        for (int j = 0; j < 8; j++) acc[i][j] = 0.f;

    for (int k0 = 0; k0 < K; k0 += KT) {
        float4 av = *(const float4*)(A + (long)lr * K + k0 + lc);
        As[lc + 0][lr] = av.x; As[lc + 1][lr] = av.y;
        As[lc + 2][lr] = av.z; As[lc + 3][lr] = av.w;

        *(float4*)&Bs[bk][bn] = *(const float4*)(Bm + (long)(k0 + bk) * 256 + n0 + bn);
        __syncthreads();

#pragma unroll
        for (int kk = 0; kk < KT; kk++) {
            float a[8], b[8];
            *(float4*)(a)     = *(const float4*)&As[kk][ty * 8];
            *(float4*)(a + 4) = *(const float4*)&As[kk][ty * 8 + 4];
            *(float4*)(b)     = *(const float4*)&Bs[kk][tx * 8];
            *(float4*)(b + 4) = *(const float4*)&Bs[kk][tx * 8 + 4];
#pragma unroll
            for (int i = 0; i < 8; i++)
#pragma unroll
                for (int j = 0; j < 8; j++)
                    acc[i][j] = fmaf(a[i], b[j], acc[i][j]);
        }
        __syncthreads();
    }

#pragma unroll
    for (int i = 0; i < 8; i++) {
        long bz = ty * 8 + i;
        float4* cp = (float4*)(g_wc + bz * 65536 + (long)i_dim * 256 + n0 + tx * 8);
        cp[0] = make_float4(acc[i][0], acc[i][1], acc[i][2], acc[i][3]);
        cp[1] = make_float4(acc[i][4], acc[i][5], acc[i][6], acc[i][7]);
    }
}

// ---------------------------------------------------------------------------
// Kernel B: per bz (blockIdx.z), NN GEMM 256x256x256:
//   C[x][j] = start[b][x][:] @ Wc[bz][:][:]
// writes t[b][x][z][j] (row stride 4096 between x's).
// ---------------------------------------------------------------------------
__global__ __launch_bounds__(256, 2)
void kernB(const float* __restrict__ start)
{
    const int K = 256;
    int bz = blockIdx.z;
    int b = bz >> 4, z = bz & 15;
    const float* A  = start + (long)b * 65536;   // [x][i]
    const float* Bm = g_wc  + (long)bz * 65536;  // [i][j]
    float* C = g_t + (long)b * 1048576 + (long)z * 256;  // +x*4096 +j

    __shared__ float As[KT][TILE];
    __shared__ float Bs[KT][TILE];

    int tid = threadIdx.x;
    int tx = tid & 15, ty = tid >> 4;
    int m0 = blockIdx.y * TILE;
    int n0 = blockIdx.x * TILE;

    int lr = tid >> 1;
    int lc = (tid & 1) * 4;
    int bk = tid >> 5;
    int bn = (tid & 31) * 4;

    float acc[8][8];
#pragma unroll
    for (int i = 0; i < 8; i++)
#pragma unroll
        for (int j = 0; j < 8; j++) acc[i][j] = 0.f;

    for (int k0 = 0; k0 < K; k0 += KT) {
        float4 av = *(const float4*)(A + (long)(m0 + lr) * K + k0 + lc);
        As[lc + 0][lr] = av.x; As[lc + 1][lr] = av.y;
        As[lc + 2][lr] = av.z; As[lc + 3][lr] = av.w;

        *(float4*)&Bs[bk][bn] = *(const float4*)(Bm + (long)(k0 + bk) * 256 + n0 + bn);
        __syncthreads();

#pragma unroll
        for (int kk = 0; kk < KT; kk++) {
            float a[8], b[8];
            *(float4*)(a)     = *(const float4*)&As[kk][ty * 8];
            *(float4*)(a + 4) = *(const float4*)&As[kk][ty * 8 + 4];
            *(float4*)(b)     = *(const float4*)&Bs[kk][tx * 8];
            *(float4*)(b + 4) = *(const float4*)&Bs[kk][tx * 8 + 4];
#pragma unroll
            for (int i = 0; i < 8; i++)
#pragma unroll
                for (int j = 0; j < 8; j++)
                    acc[i][j] = fmaf(a[i], b[j], acc[i][j]);
        }
        __syncthreads();
    }

#pragma unroll
    for (int i = 0; i < 8; i++) {
        long x = m0 + ty * 8 + i;
        float4* cp = (float4*)(C + x * 4096 + n0 + tx * 8);
        cp[0] = make_float4(acc[i][0], acc[i][1], acc[i][2], acc[i][3]);
        cp[1] = make_float4(acc[i][4], acc[i][5], acc[i][6], acc[i][7]);
    }
}

// ---------------------------------------------------------------------------
// Kernel C: per b (blockIdx.z), NT GEMM M=4096 (m = x*16+z), N=256 (y), K=256 (j):
//   C[m][y] = t[b][m][:] . end[b][y][:]
// Output out[b][x][y][z]: addr = b*1048576 + (m>>4)*4096 + y*16 + (m&15).
// Per-thread 8 consecutive m = 8 consecutive z (same x) -> float4 stores in z.
// ---------------------------------------------------------------------------
__global__ __launch_bounds__(256, 2)
void kernC(const float* __restrict__ endl, float* __restrict__ out)
{
    const int K = 256;
    int b = blockIdx.z;
    const float* A  = g_t  + (long)b * 1048576;  // [m=4096][j=256]
    const float* Bm = endl + (long)b * 65536;    // [y][j]
    float* O = out + (long)b * 1048576;          // per-b slab: 256*256*16

    __shared__ float As[KT][TILE];
    __shared__ float Bs[KT][TILE];

    int tid = threadIdx.x;
    int tx = tid & 15, ty = tid >> 4;
    int m0 = blockIdx.y * TILE;
    int n0 = blockIdx.x * TILE;

    int lr = tid >> 1;
    int lc = (tid & 1) * 4;

    float acc[8][8];
#pragma unroll
    for (int i = 0; i < 8; i++)
#pragma unroll
        for (int j = 0; j < 8; j++) acc[i][j] = 0.f;

    for (int k0 = 0; k0 < K; k0 += KT) {
        float4 av = *(const float4*)(A + (long)(m0 + lr) * K + k0 + lc);
        As[lc + 0][lr] = av.x; As[lc + 1][lr] = av.y;
        As[lc + 2][lr] = av.z; As[lc + 3][lr] = av.w;

        float4 bv = *(const float4*)(Bm + (long)(n0 + lr) * K + k0 + lc);
        Bs[lc + 0][lr] = bv.x; Bs[lc + 1][lr] = bv.y;
        Bs[lc + 2][lr] = bv.z; Bs[lc + 3][lr] = bv.w;
        __syncthreads();

#pragma unroll
        for (int kk = 0; kk < KT; kk++) {
            float a[8], b2[8];
            *(float4*)(a)      = *(const float4*)&As[kk][ty * 8];
            *(float4*)(a + 4)  = *(const float4*)&As[kk][ty * 8 + 4];
            *(float4*)(b2)     = *(const float4*)&Bs[kk][tx * 8];
            *(float4*)(b2 + 4) = *(const float4*)&Bs[kk][tx * 8 + 4];
#pragma unroll
            for (int i = 0; i < 8; i++)
#pragma unroll
                for (int j = 0; j < 8; j++)
                    acc[i][j] = fmaf(a[i], b2[j], acc[i][j]);
        }
        __syncthreads();
    }

    // m block: 8 consecutive m = same x, z0 = 0 or 8
    int m = m0 + ty * 8;
    long x  = m >> 4;
    int  z0 = m & 15;
#pragma unroll
    for (int j = 0; j < 8; j++) {
        long y = n0 + tx * 8 + j;
        float* p = O + x * 4096 + y * 16 + z0;
        *(float4*)(p)     = make_float4(acc[0][j], acc[1][j], acc[2][j], acc[3][j]);
        *(float4*)(p + 4) = make_float4(acc[4][j], acc[5][j], acc[6][j], acc[7][j]);
    }
}

extern "C" void kernel_launch(void* const* d_in, const int* in_sizes, int n_in,
                              void* d_out, int out_size)
{
    const float* start = (const float*)d_in[0];   // [8,256,256]
    const float* endl  = (const float*)d_in[1];   // [8,256,256]
    const float* cls   = (const float*)d_in[2];   // [8,16,256]
    const float* W     = (const float*)d_in[3];   // [256,256,256]
    float* out = (float*)d_out;                   // [8,256,256,16]

    dim3 gA(2, 1, 256);     // N tiles, -, i
    kernA<<<gA, 256>>>(cls, W);

    dim3 gB(2, 2, 128);     // N, M, bz
    kernB<<<gB, 256>>>(start);

    dim3 gC(2, 32, 8);      // N, M(4096/128), b
    kernC<<<gC, 256>>>(endl, out);
}

// round 4
// speedup vs baseline: 9.3931x; 1.0079x over previous
#include <cuda_runtime.h>

// Problem: B=8, L=256, Z=16, H=256
// Reassociated contraction order (12.9 GFLOP total):
//   A: Wc[bz][i][j] = sum_o cls[bz][o] * W[i][o][j]         (per i: GEMM 128x256x256)
//   B: t[b][x][z][j] = sum_i start[b][x][i] * Wc[bz][i][j]  (per bz: GEMM 256x256x256 NN)
//   C: out[b][x][y][z] = sum_j t[b][x][z][j] * end[b][y][j] (per b:  GEMM 4096x256x256 NT)
// Inner loops use packed f32x2 FMA (FFMA2) -> 2x fp32 throughput vs scalar FFMA.

__device__ float g_wc[8388608];   // [bz=128][i=256][j=256]
__device__ float g_t [8388608];   // [b=8][x=256][z=16][j=256]

#define TILE 128
#define KT   8

typedef unsigned long long u64;

// duplicate one fp32 into both lanes of a b64 (f32x2) register
__device__ __forceinline__ u64 dupf(float v) {
    u64 r; unsigned u = __float_as_uint(v);
    asm("mov.b64 %0, {%1, %1};" : "=l"(r) : "r"(u));
    return r;
}
// packed dual FMA: d.lo += a.lo*b.lo ; d.hi += a.hi*b.hi
__device__ __forceinline__ void fma2(u64& d, u64 a, u64 b) {
    asm("fma.rn.f32x2 %0, %1, %2, %0;" : "+l"(d) : "l"(a), "l"(b));
}
__device__ __forceinline__ void unpk(u64 v, float& lo, float& hi) {
    unsigned l, h;
    asm("mov.b64 {%0, %1}, %2;" : "=r"(l), "=r"(h) : "l"(v));
    lo = __uint_as_float(l); hi = __uint_as_float(h);
}

// Micro-kernel: consume one KTx128 As/Bs stage.
// acc[ip][j] packs rows (ty*8+2ip, ty*8+2ip+1) for column tx*8+j.
__device__ __forceinline__ void mk_compute(const float (*As)[TILE], const float (*Bs)[TILE],
                                           int tx, int ty, u64 acc[4][8])
{
#pragma unroll
    for (int kk = 0; kk < KT; kk++) {
        ulonglong2 a01 = *(const ulonglong2*)&As[kk][ty * 8];
        ulonglong2 a23 = *(const ulonglong2*)&As[kk][ty * 8 + 4];
        u64 ap[4]; ap[0] = a01.x; ap[1] = a01.y; ap[2] = a23.x; ap[3] = a23.y;
        float4 b0 = *(const float4*)&Bs[kk][tx * 8];
        float4 b1 = *(const float4*)&Bs[kk][tx * 8 + 4];
        u64 bd[8];
        bd[0] = dupf(b0.x); bd[1] = dupf(b0.y); bd[2] = dupf(b0.z); bd[3] = dupf(b0.w);
        bd[4] = dupf(b1.x); bd[5] = dupf(b1.y); bd[6] = dupf(b1.z); bd[7] = dupf(b1.w);
#pragma unroll
        for (int ip = 0; ip < 4; ip++)
#pragma unroll
            for (int j = 0; j < 8; j++)
                fma2(acc[ip][j], ap[ip], bd[j]);
    }
}

__device__ __forceinline__ void mk_unpack(u64 acc[4][8], float c[8][8])
{
#pragma unroll
    for (int ip = 0; ip < 4; ip++)
#pragma unroll
        for (int j = 0; j < 8; j++)
            unpk(acc[ip][j], c[2 * ip][j], c[2 * ip + 1][j]);
}

// ---------------------------------------------------------------------------
// Kernel A: per i (blockIdx.z), C[bz][j] = cls[bz][:] @ W[i][:][:]
// ---------------------------------------------------------------------------
__global__ __launch_bounds__(256, 2)
void kernA(const float* __restrict__ cls, const float* __restrict__ W)
{
    const int K = 256;
    int i_dim = blockIdx.z;
    const float* A  = cls;                        // [128][256]
    const float* Bm = W + (long)i_dim * 65536;    // [o=256][j=256]

    __shared__ float As[KT][TILE];
    __shared__ float Bs[KT][TILE];

    int tid = threadIdx.x;
    int tx = tid & 15, ty = tid >> 4;
    int n0 = blockIdx.x * TILE;

    int lr = tid >> 1;          // 0..127
    int lc = (tid & 1) * 4;     // 0 or 4
    int bk = tid >> 5;          // 0..7
    int bn = (tid & 31) * 4;    // 0..124

    u64 acc[4][8];
#pragma unroll
    for (int ip = 0; ip < 4; ip++)
#pragma unroll
        for (int j = 0; j < 8; j++) acc[ip][j] = 0ULL;

    for (int k0 = 0; k0 < K; k0 += KT) {
        float4 av = *(const float4*)(A + (long)lr * K + k0 + lc);
        As[lc + 0][lr] = av.x; As[lc + 1][lr] = av.y;
        As[lc + 2][lr] = av.z; As[lc + 3][lr] = av.w;
        *(float4*)&Bs[bk][bn] = *(const float4*)(Bm + (long)(k0 + bk) * 256 + n0 + bn);
        __syncthreads();
        mk_compute(As, Bs, tx, ty, acc);
        __syncthreads();
    }

    float c[8][8];
    mk_unpack(acc, c);
#pragma unroll
    for (int i = 0; i < 8; i++) {
        long bz = ty * 8 + i;
        float4* cp = (float4*)(g_wc + bz * 65536 + (long)i_dim * 256 + n0 + tx * 8);
        cp[0] = make_float4(c[i][0], c[i][1], c[i][2], c[i][3]);
        cp[1] = make_float4(c[i][4], c[i][5], c[i][6], c[i][7]);
    }
}

// ---------------------------------------------------------------------------
// Kernel B: per bz (blockIdx.z), NN GEMM 256x256x256:
//   C[x][j] = start[b][x][:] @ Wc[bz][:][:]   ->  t[b][x][z][j]
// ---------------------------------------------------------------------------
__global__ __launch_bounds__(256, 2)
void kernB(const float* __restrict__ start)
{
    const int K = 256;
    int bz = blockIdx.z;
    int b = bz >> 4, z = bz & 15;
    const float* A  = start + (long)b * 65536;    // [x][i]
    const float* Bm = g_wc  + (long)bz * 65536;   // [i][j]
    float* C = g_t + (long)b * 1048576 + (long)z * 256;   // +x*4096 +j

    __shared__ float As[KT][TILE];
    __shared__ float Bs[KT][TILE];

    int tid = threadIdx.x;
    int tx = tid & 15, ty = tid >> 4;
    int m0 = blockIdx.y * TILE;
    int n0 = blockIdx.x * TILE;

    int lr = tid >> 1;
    int lc = (tid & 1) * 4;
    int bk = tid >> 5;
    int bn = (tid & 31) * 4;

    u64 acc[4][8];
#pragma unroll
    for (int ip = 0; ip < 4; ip++)
#pragma unroll
        for (int j = 0; j < 8; j++) acc[ip][j] = 0ULL;

    for (int k0 = 0; k0 < K; k0 += KT) {
        float4 av = *(const float4*)(A + (long)(m0 + lr) * K + k0 + lc);
        As[lc + 0][lr] = av.x; As[lc + 1][lr] = av.y;
        As[lc + 2][lr] = av.z; As[lc + 3][lr] = av.w;
        *(float4*)&Bs[bk][bn] = *(const float4*)(Bm + (long)(k0 + bk) * 256 + n0 + bn);
        __syncthreads();
        mk_compute(As, Bs, tx, ty, acc);
        __syncthreads();
    }

    float c[8][8];
    mk_unpack(acc, c);
#pragma unroll
    for (int i = 0; i < 8; i++) {
        long x = m0 + ty * 8 + i;
        float4* cp = (float4*)(C + x * 4096 + n0 + tx * 8);
        cp[0] = make_float4(c[i][0], c[i][1], c[i][2], c[i][3]);
        cp[1] = make_float4(c[i][4], c[i][5], c[i][6], c[i][7]);
    }
}

// ---------------------------------------------------------------------------
// Kernel C: per b (blockIdx.z), NT GEMM M=4096 (m=x*16+z), N=256 (y), K=256 (j):
//   C[m][y] = t[b][m][:] . end[b][y][:]
// out[b][x][y][z]: addr = b*1048576 + x*4096 + y*16 + z.
// ---------------------------------------------------------------------------
__global__ __launch_bounds__(256, 2)
void kernC(const float* __restrict__ endl, float* __restrict__ out)
{
    const int K = 256;
    int b = blockIdx.z;
    const float* A  = g_t  + (long)b * 1048576;   // [m=4096][j=256]
    const float* Bm = endl + (long)b * 65536;     // [y][j]
    float* O = out + (long)b * 1048576;           // per-b slab 256*256*16

    __shared__ float As[KT][TILE];
    __shared__ float Bs[KT][TILE];

    int tid = threadIdx.x;
    int tx = tid & 15, ty = tid >> 4;
    int m0 = blockIdx.y * TILE;
    int n0 = blockIdx.x * TILE;

    int lr = tid >> 1;
    int lc = (tid & 1) * 4;

    u64 acc[4][8];
#pragma unroll
    for (int ip = 0; ip < 4; ip++)
#pragma unroll
        for (int j = 0; j < 8; j++) acc[ip][j] = 0ULL;

    for (int k0 = 0; k0 < K; k0 += KT) {
        float4 av = *(const float4*)(A + (long)(m0 + lr) * K + k0 + lc);
        As[lc + 0][lr] = av.x; As[lc + 1][lr] = av.y;
        As[lc + 2][lr] = av.z; As[lc + 3][lr] = av.w;

        float4 bv = *(const float4*)(Bm + (long)(n0 + lr) * K + k0 + lc);
        Bs[lc + 0][lr] = bv.x; Bs[lc + 1][lr] = bv.y;
        Bs[lc + 2][lr] = bv.z; Bs[lc + 3][lr] = bv.w;
        __syncthreads();
        mk_compute(As, Bs, tx, ty, acc);
        __syncthreads();
    }

    float c[8][8];
    mk_unpack(acc, c);

    // 8 consecutive m = same x, z0 = 0 or 8
    int m = m0 + ty * 8;
    long x  = m >> 4;
    int  z0 = m & 15;
#pragma unroll
    for (int j = 0; j < 8; j++) {
        long y = n0 + tx * 8 + j;
        float* p = O + x * 4096 + y * 16 + z0;
        *(float4*)(p)     = make_float4(c[0][j], c[1][j], c[2][j], c[3][j]);
        *(float4*)(p + 4) = make_float4(c[4][j], c[5][j], c[6][j], c[7][j]);
    }
}

extern "C" void kernel_launch(void* const* d_in, const int* in_sizes, int n_in,
                              void* d_out, int out_size)
{
    const float* start = (const float*)d_in[0];   // [8,256,256]
    const float* endl  = (const float*)d_in[1];   // [8,256,256]
    const float* cls   = (const float*)d_in[2];   // [8,16,256]
    const float* W     = (const float*)d_in[3];   // [256,256,256]
    float* out = (float*)d_out;                   // [8,256,256,16]

    dim3 gA(2, 1, 256);     // j tiles, -, i
    kernA<<<gA, 256>>>(cls, W);

    dim3 gB(2, 2, 128);     // j, x, bz
    kernB<<<gB, 256>>>(start);

    dim3 gC(2, 32, 8);      // y, m(4096/128), b
    kernC<<<gC, 256>>>(endl, out);
}

// round 5
// speedup vs baseline: 10.3444x; 1.1013x over previous
#include <cuda_runtime.h>

// Problem: B=8, L=256, Z=16, H=256
// Reassociated contraction order (12.9 GFLOP total):
//   A: Wc[bz][i][j] = sum_o cls[bz][o] * W[i][o][j]         (per i: GEMM 128x256x256)
//   B: t[b][x][z][j] = sum_i start[b][x][i] * Wc[bz][i][j]  (per bz: GEMM 256x256x256 NN)
//   C: out[b][x][y][z] = sum_j t[b][x][z][j] * end[b][y][j] (per b:  GEMM 4096x256x256 NT)
// FFMA2 (packed f32x2) inner loop + double-buffered smem pipeline.

__device__ float g_wc[8388608];   // [bz=128][i=256][j=256]
__device__ float g_t [8388608];   // [b=8][x=256][z=16][j=256]

#define TILE 128
#define KT   8
#define NSTAGE 32                 // 256 / KT

typedef unsigned long long u64;

__device__ __forceinline__ u64 dupf(float v) {
    u64 r; unsigned u = __float_as_uint(v);
    asm("mov.b64 %0, {%1, %1};" : "=l"(r) : "r"(u));
    return r;
}
__device__ __forceinline__ void fma2(u64& d, u64 a, u64 b) {
    asm("fma.rn.f32x2 %0, %1, %2, %0;" : "+l"(d) : "l"(a), "l"(b));
}
__device__ __forceinline__ void unpk(u64 v, float& lo, float& hi) {
    unsigned l, h;
    asm("mov.b64 {%0, %1}, %2;" : "=r"(l), "=r"(h) : "l"(v));
    lo = __uint_as_float(l); hi = __uint_as_float(h);
}

// consume one KTx128 stage; acc[ip][j] packs rows (ty*8+2ip, +1) x col (tx*8+j)
__device__ __forceinline__ void mk_compute(const float (*As)[TILE], const float (*Bs)[TILE],
                                           int tx, int ty, u64 acc[4][8])
{
#pragma unroll
    for (int kk = 0; kk < KT; kk++) {
        ulonglong2 a01 = *(const ulonglong2*)&As[kk][ty * 8];
        ulonglong2 a23 = *(const ulonglong2*)&As[kk][ty * 8 + 4];
        u64 ap[4]; ap[0] = a01.x; ap[1] = a01.y; ap[2] = a23.x; ap[3] = a23.y;
        float4 b0 = *(const float4*)&Bs[kk][tx * 8];
        float4 b1 = *(const float4*)&Bs[kk][tx * 8 + 4];
        u64 bd[8];
        bd[0] = dupf(b0.x); bd[1] = dupf(b0.y); bd[2] = dupf(b0.z); bd[3] = dupf(b0.w);
        bd[4] = dupf(b1.x); bd[5] = dupf(b1.y); bd[6] = dupf(b1.z); bd[7] = dupf(b1.w);
#pragma unroll
        for (int ip = 0; ip < 4; ip++)
#pragma unroll
            for (int j = 0; j < 8; j++)
                fma2(acc[ip][j], ap[ip], bd[j]);
    }
}

__device__ __forceinline__ void mk_unpack(u64 acc[4][8], float c[8][8])
{
#pragma unroll
    for (int ip = 0; ip < 4; ip++)
#pragma unroll
        for (int j = 0; j < 8; j++)
            unpk(acc[ip][j], c[2 * ip][j], c[2 * ip + 1][j]);
}

// ---------------------------------------------------------------------------
// Kernel A: per i (blockIdx.z), C[bz][j] = cls[bz][:] @ W[i][:][:]
// A transposed into As; B direct rows. Double buffered.
// ---------------------------------------------------------------------------
__global__ __launch_bounds__(256, 2)
void kernA(const float* __restrict__ cls, const float* __restrict__ W)
{
    int i_dim = blockIdx.z;
    const float* A  = cls;                        // [128][256]
    const float* Bm = W + (long)i_dim * 65536;    // [o=256][j=256]

    __shared__ float As[2][KT][TILE];
    __shared__ float Bs[2][KT][TILE];

    int tid = threadIdx.x;
    int tx = tid & 15, ty = tid >> 4;
    int n0 = blockIdx.x * TILE;

    int lr = tid >> 1;          // 0..127
    int lc = (tid & 1) * 4;     // 0 or 4
    int bk = tid >> 5;          // 0..7
    int bn = (tid & 31) * 4;    // 0..124

    u64 acc[4][8];
#pragma unroll
    for (int ip = 0; ip < 4; ip++)
#pragma unroll
        for (int j = 0; j < 8; j++) acc[ip][j] = 0ULL;

    // prologue: stage 0
    {
        float4 av = *(const float4*)(A + (long)lr * 256 + lc);
        As[0][lc + 0][lr] = av.x; As[0][lc + 1][lr] = av.y;
        As[0][lc + 2][lr] = av.z; As[0][lc + 3][lr] = av.w;
        *(float4*)&Bs[0][bk][bn] = *(const float4*)(Bm + (long)bk * 256 + n0 + bn);
    }
    __syncthreads();

    int buf = 0;
#pragma unroll 2
    for (int s = 0; s < NSTAGE; s++) {
        float4 nav, nbv;
        if (s + 1 < NSTAGE) {
            int k1 = (s + 1) * KT;
            nav = *(const float4*)(A + (long)lr * 256 + k1 + lc);
            nbv = *(const float4*)(Bm + (long)(k1 + bk) * 256 + n0 + bn);
        }
        mk_compute(As[buf], Bs[buf], tx, ty, acc);
        if (s + 1 < NSTAGE) {
            int nb = buf ^ 1;
            As[nb][lc + 0][lr] = nav.x; As[nb][lc + 1][lr] = nav.y;
            As[nb][lc + 2][lr] = nav.z; As[nb][lc + 3][lr] = nav.w;
            *(float4*)&Bs[nb][bk][bn] = nbv;
            __syncthreads();
            buf = nb;
        }
    }

    float c[8][8];
    mk_unpack(acc, c);
#pragma unroll
    for (int i = 0; i < 8; i++) {
        long bz = ty * 8 + i;
        float4* cp = (float4*)(g_wc + bz * 65536 + (long)i_dim * 256 + n0 + tx * 8);
        cp[0] = make_float4(c[i][0], c[i][1], c[i][2], c[i][3]);
        cp[1] = make_float4(c[i][4], c[i][5], c[i][6], c[i][7]);
    }
}

// ---------------------------------------------------------------------------
// Kernel B: per bz (blockIdx.z), NN GEMM 256x256x256:
//   C[x][j] = start[b][x][:] @ Wc[bz][:][:]   ->  t[b][x][z][j]
// ---------------------------------------------------------------------------
__global__ __launch_bounds__(256, 2)
void kernB(const float* __restrict__ start)
{
    int bz = blockIdx.z;
    int b = bz >> 4, z = bz & 15;
    const float* A  = start + (long)b * 65536;    // [x][i]
    const float* Bm = g_wc  + (long)bz * 65536;   // [i][j]
    float* C = g_t + (long)b * 1048576 + (long)z * 256;   // +x*4096 +j

    __shared__ float As[2][KT][TILE];
    __shared__ float Bs[2][KT][TILE];

    int tid = threadIdx.x;
    int tx = tid & 15, ty = tid >> 4;
    int m0 = blockIdx.y * TILE;
    int n0 = blockIdx.x * TILE;

    int lr = tid >> 1;
    int lc = (tid & 1) * 4;
    int bk = tid >> 5;
    int bn = (tid & 31) * 4;

    u64 acc[4][8];
#pragma unroll
    for (int ip = 0; ip < 4; ip++)
#pragma unroll
        for (int j = 0; j < 8; j++) acc[ip][j] = 0ULL;

    {
        float4 av = *(const float4*)(A + (long)(m0 + lr) * 256 + lc);
        As[0][lc + 0][lr] = av.x; As[0][lc + 1][lr] = av.y;
        As[0][lc + 2][lr] = av.z; As[0][lc + 3][lr] = av.w;
        *(float4*)&Bs[0][bk][bn] = *(const float4*)(Bm + (long)bk * 256 + n0 + bn);
    }
    __syncthreads();

    int buf = 0;
#pragma unroll 2
    for (int s = 0; s < NSTAGE; s++) {
        float4 nav, nbv;
        if (s + 1 < NSTAGE) {
            int k1 = (s + 1) * KT;
            nav = *(const float4*)(A + (long)(m0 + lr) * 256 + k1 + lc);
            nbv = *(const float4*)(Bm + (long)(k1 + bk) * 256 + n0 + bn);
        }
        mk_compute(As[buf], Bs[buf], tx, ty, acc);
        if (s + 1 < NSTAGE) {
            int nb = buf ^ 1;
            As[nb][lc + 0][lr] = nav.x; As[nb][lc + 1][lr] = nav.y;
            As[nb][lc + 2][lr] = nav.z; As[nb][lc + 3][lr] = nav.w;
            *(float4*)&Bs[nb][bk][bn] = nbv;
            __syncthreads();
            buf = nb;
        }
    }

    float c[8][8];
    mk_unpack(acc, c);
#pragma unroll
    for (int i = 0; i < 8; i++) {
        long x = m0 + ty * 8 + i;
        float4* cp = (float4*)(C + x * 4096 + n0 + tx * 8);
        cp[0] = make_float4(c[i][0], c[i][1], c[i][2], c[i][3]);
        cp[1] = make_float4(c[i][4], c[i][5], c[i][6], c[i][7]);
    }
}

// ---------------------------------------------------------------------------
// Kernel C: per b (blockIdx.z), NT GEMM M=4096 (m=x*16+z), N=256 (y), K=256 (j):
//   C[m][y] = t[b][m][:] . end[b][y][:]
// out[b][x][y][z]: addr = b*1048576 + x*4096 + y*16 + z.
// ---------------------------------------------------------------------------
__global__ __launch_bounds__(256, 2)
void kernC(const float* __restrict__ endl, float* __restrict__ out)
{
    int b = blockIdx.z;
    const float* A  = g_t  + (long)b * 1048576;   // [m=4096][j=256]
    const float* Bm = endl + (long)b * 65536;     // [y][j]
    float* O = out + (long)b * 1048576;           // per-b slab 256*256*16

    __shared__ float As[2][KT][TILE];
    __shared__ float Bs[2][KT][TILE];

    int tid = threadIdx.x;
    int tx = tid & 15, ty = tid >> 4;
    int m0 = blockIdx.y * TILE;
    int n0 = blockIdx.x * TILE;

    int lr = tid >> 1;
    int lc = (tid & 1) * 4;

    u64 acc[4][8];
#pragma unroll
    for (int ip = 0; ip < 4; ip++)
#pragma unroll
        for (int j = 0; j < 8; j++) acc[ip][j] = 0ULL;

    {
        float4 av = *(const float4*)(A + (long)(m0 + lr) * 256 + lc);
        As[0][lc + 0][lr] = av.x; As[0][lc + 1][lr] = av.y;
        As[0][lc + 2][lr] = av.z; As[0][lc + 3][lr] = av.w;
        float4 bv = *(const float4*)(Bm + (long)(n0 + lr) * 256 + lc);
        Bs[0][lc + 0][lr] = bv.x; Bs[0][lc + 1][lr] = bv.y;
        Bs[0][lc + 2][lr] = bv.z; Bs[0][lc + 3][lr] = bv.w;
    }
    __syncthreads();

    int buf = 0;
#pragma unroll 2
    for (int s = 0; s < NSTAGE; s++) {
        float4 nav, nbv;
        if (s + 1 < NSTAGE) {
            int k1 = (s + 1) * KT;
            nav = *(const float4*)(A + (long)(m0 + lr) * 256 + k1 + lc);
            nbv = *(const float4*)(Bm + (long)(n0 + lr) * 256 + k1 + lc);
        }
        mk_compute(As[buf], Bs[buf], tx, ty, acc);
        if (s + 1 < NSTAGE) {
            int nb = buf ^ 1;
            As[nb][lc + 0][lr] = nav.x; As[nb][lc + 1][lr] = nav.y;
            As[nb][lc + 2][lr] = nav.z; As[nb][lc + 3][lr] = nav.w;
            Bs[nb][lc + 0][lr] = nbv.x; Bs[nb][lc + 1][lr] = nbv.y;
            Bs[nb][lc + 2][lr] = nbv.z; Bs[nb][lc + 3][lr] = nbv.w;
            __syncthreads();
            buf = nb;
        }
    }

    float c[8][8];
    mk_unpack(acc, c);

    // 8 consecutive m = same x, z0 = 0 or 8
    int m = m0 + ty * 8;
    long x  = m >> 4;
    int  z0 = m & 15;
#pragma unroll
    for (int j = 0; j < 8; j++) {
        long y = n0 + tx * 8 + j;
        float* p = O + x * 4096 + y * 16 + z0;
        *(float4*)(p)     = make_float4(c[0][j], c[1][j], c[2][j], c[3][j]);
        *(float4*)(p + 4) = make_float4(c[4][j], c[5][j], c[6][j], c[7][j]);
    }
}

extern "C" void kernel_launch(void* const* d_in, const int* in_sizes, int n_in,
                              void* d_out, int out_size)
{
    const float* start = (const float*)d_in[0];   // [8,256,256]
    const float* endl  = (const float*)d_in[1];   // [8,256,256]
    const float* cls   = (const float*)d_in[2];   // [8,16,256]
    const float* W     = (const float*)d_in[3];   // [256,256,256]
    float* out = (float*)d_out;                   // [8,256,256,16]

    dim3 gA(2, 1, 256);     // j tiles, -, i
    kernA<<<gA, 256>>>(cls, W);

    dim3 gB(2, 2, 128);     // j, x, bz
    kernB<<<gB, 256>>>(start);

    dim3 gC(2, 32, 8);      // y, m(4096/128), b
    kernC<<<gC, 256>>>(endl, out);
}